// round 16
// baseline (speedup 1.0000x reference)
#include <cuda_runtime.h>
#include <cstdint>

#define NN 10000
#define HH 128
#define EE 640000
#define E2 (EE + NN)

typedef unsigned long long ull;

// ---------------- device scratch ----------------
__device__ float g_xl[NN * HH];
__device__ float g_xr[NN * HH];
__device__ float g_ez[E2];
__device__ float g_denom[NN];
__device__ int   g_count[NN];
__device__ int   g_rowstart[NN + 1];
__device__ int   g_csr_src[E2];
__device__ float g_csr_ez[E2];
__device__ float g_hgat[NN * HH];
__device__ float g_gi[NN * 3 * HH];
__device__ float g_hseq[NN * HH];

// ---------------- helpers ----------------
__device__ __forceinline__ ull ffma2(ull a, ull b, ull c) {
    ull d;
    asm("fma.rn.f32x2 %0, %1, %2, %3;" : "=l"(d) : "l"(a), "l"(b), "l"(c));
    return d;
}
__device__ __forceinline__ ull fadd2(ull a, ull b) {
    ull d;
    asm("add.rn.f32x2 %0, %1, %2;" : "=l"(d) : "l"(a), "l"(b));
    return d;
}
__device__ __forceinline__ float unpack_sum(ull a) {
    unsigned lo, hi;
    asm("mov.b64 {%0,%1}, %2;" : "=r"(lo), "=r"(hi) : "l"(a));
    return __uint_as_float(lo) + __uint_as_float(hi);
}
__device__ __forceinline__ float sigf(float x) {
    return __fdividef(1.f, 1.f + __expf(-x));
}
__device__ __forceinline__ float tanhfast(float x) {
    return 2.f * __fdividef(1.f, 1.f + __expf(-2.f * x)) - 1.f;
}
__device__ __forceinline__ float lrelu(float v) {
    return v > 0.f ? v : 0.2f * v;
}
__device__ __forceinline__ int clampN(int v) {
    return v < 0 ? 0 : (v >= NN ? NN - 1 : v);
}

// ---------------- zero init (+ out, for atomic head) ----------------
__global__ void zero_kernel(float* __restrict__ out) {
    int i = blockIdx.x * blockDim.x + threadIdx.x;
    if (i < NN) {
        g_denom[i] = 0.f;
        g_count[i] = 0;
        out[i] = 0.f;
    }
}

// ---------------- GEMM: C[M x P] = A[M x 128] @ W[P x 128]^T + bias ----------------
template <int P, bool RELU>
__global__ void __launch_bounds__(256) gemm_tn(const float* __restrict__ A,
                                               const float* __restrict__ W,
                                               const float* __restrict__ bias,
                                               float* __restrict__ C, int M) {
    __shared__ __align__(16) float As[32][68];
    __shared__ __align__(16) float Ws[32][68];
    const int tid = threadIdx.x;
    const int bm = blockIdx.x * 64;
    const int bp = blockIdx.y * 64;
    const int tx = tid & 15;
    const int ty = tid >> 4;
    float acc[4][4];
#pragma unroll
    for (int i = 0; i < 4; i++)
#pragma unroll
        for (int j = 0; j < 4; j++) acc[i][j] = 0.f;

    const int r = tid >> 3;
    const int kk = (tid & 7) * 4;

    for (int k0 = 0; k0 < 128; k0 += 32) {
#pragma unroll
        for (int rr = 0; rr < 64; rr += 32) {
            int row = bm + r + rr;
            float4 v = (row < M) ? *reinterpret_cast<const float4*>(A + (size_t)row * 128 + k0 + kk)
                                 : make_float4(0.f, 0.f, 0.f, 0.f);
            As[kk + 0][r + rr] = v.x;
            As[kk + 1][r + rr] = v.y;
            As[kk + 2][r + rr] = v.z;
            As[kk + 3][r + rr] = v.w;
            float4 wv = *reinterpret_cast<const float4*>(W + (size_t)(bp + r + rr) * 128 + k0 + kk);
            Ws[kk + 0][r + rr] = wv.x;
            Ws[kk + 1][r + rr] = wv.y;
            Ws[kk + 2][r + rr] = wv.z;
            Ws[kk + 3][r + rr] = wv.w;
        }
        __syncthreads();
#pragma unroll
        for (int k = 0; k < 32; k++) {
            const float4 av = *reinterpret_cast<const float4*>(&As[k][ty << 2]);
            const float4 wv = *reinterpret_cast<const float4*>(&Ws[k][tx << 2]);
            float a4[4] = {av.x, av.y, av.z, av.w};
            float w4[4] = {wv.x, wv.y, wv.z, wv.w};
#pragma unroll
            for (int i = 0; i < 4; i++)
#pragma unroll
                for (int j = 0; j < 4; j++) acc[i][j] += a4[i] * w4[j];
        }
        __syncthreads();
    }

    const int col0 = bp + (tx << 2);
    const float4 bv = *reinterpret_cast<const float4*>(bias + col0);
    float b4[4] = {bv.x, bv.y, bv.z, bv.w};
#pragma unroll
    for (int i = 0; i < 4; i++) {
        int row = bm + (ty << 2) + i;
        if (row < M) {
            float4 o;
            float v0 = acc[i][0] + b4[0];
            float v1 = acc[i][1] + b4[1];
            float v2 = acc[i][2] + b4[2];
            float v3 = acc[i][3] + b4[3];
            if (RELU) {
                v0 = fmaxf(v0, 0.f); v1 = fmaxf(v1, 0.f);
                v2 = fmaxf(v2, 0.f); v3 = fmaxf(v3, 0.f);
            }
            o.x = v0; o.y = v1; o.z = v2; o.w = v3;
            *reinterpret_cast<float4*>(C + (size_t)row * P + col0) = o;
        }
    }
}

// ---------------- dual GEMM: xl = A@Wl^T+bl, xr = A@Wr^T+br (A tile loaded once) ----
__global__ void __launch_bounds__(256) gemm_dual(const float* __restrict__ A,
                                                 const float* __restrict__ Wl,
                                                 const float* __restrict__ bl,
                                                 const float* __restrict__ Wr,
                                                 const float* __restrict__ br,
                                                 float* __restrict__ Cl,
                                                 float* __restrict__ Cr, int M) {
    __shared__ __align__(16) float As[32][68];
    __shared__ __align__(16) float Wsl[32][68];
    __shared__ __align__(16) float Wsr[32][68];
    const int tid = threadIdx.x;
    const int bm = blockIdx.x * 64;
    const int bp = blockIdx.y * 64;
    const int tx = tid & 15;
    const int ty = tid >> 4;
    float accl[4][4], accr[4][4];
#pragma unroll
    for (int i = 0; i < 4; i++)
#pragma unroll
        for (int j = 0; j < 4; j++) { accl[i][j] = 0.f; accr[i][j] = 0.f; }

    const int r = tid >> 3;
    const int kk = (tid & 7) * 4;

    for (int k0 = 0; k0 < 128; k0 += 32) {
#pragma unroll
        for (int rr = 0; rr < 64; rr += 32) {
            int row = bm + r + rr;
            float4 v = (row < M) ? *reinterpret_cast<const float4*>(A + (size_t)row * 128 + k0 + kk)
                                 : make_float4(0.f, 0.f, 0.f, 0.f);
            As[kk + 0][r + rr] = v.x;
            As[kk + 1][r + rr] = v.y;
            As[kk + 2][r + rr] = v.z;
            As[kk + 3][r + rr] = v.w;
            float4 wl = *reinterpret_cast<const float4*>(Wl + (size_t)(bp + r + rr) * 128 + k0 + kk);
            Wsl[kk + 0][r + rr] = wl.x;
            Wsl[kk + 1][r + rr] = wl.y;
            Wsl[kk + 2][r + rr] = wl.z;
            Wsl[kk + 3][r + rr] = wl.w;
            float4 wr = *reinterpret_cast<const float4*>(Wr + (size_t)(bp + r + rr) * 128 + k0 + kk);
            Wsr[kk + 0][r + rr] = wr.x;
            Wsr[kk + 1][r + rr] = wr.y;
            Wsr[kk + 2][r + rr] = wr.z;
            Wsr[kk + 3][r + rr] = wr.w;
        }
        __syncthreads();
#pragma unroll
        for (int k = 0; k < 32; k++) {
            const float4 av = *reinterpret_cast<const float4*>(&As[k][ty << 2]);
            const float4 wl = *reinterpret_cast<const float4*>(&Wsl[k][tx << 2]);
            const float4 wr = *reinterpret_cast<const float4*>(&Wsr[k][tx << 2]);
            float a4[4] = {av.x, av.y, av.z, av.w};
            float l4[4] = {wl.x, wl.y, wl.z, wl.w};
            float r4[4] = {wr.x, wr.y, wr.z, wr.w};
#pragma unroll
            for (int i = 0; i < 4; i++)
#pragma unroll
                for (int j = 0; j < 4; j++) {
                    accl[i][j] += a4[i] * l4[j];
                    accr[i][j] += a4[i] * r4[j];
                }
        }
        __syncthreads();
    }

    const int col0 = bp + (tx << 2);
    const float4 bvl = *reinterpret_cast<const float4*>(bl + col0);
    const float4 bvr = *reinterpret_cast<const float4*>(br + col0);
    float l4[4] = {bvl.x, bvl.y, bvl.z, bvl.w};
    float r4[4] = {bvr.x, bvr.y, bvr.z, bvr.w};
#pragma unroll
    for (int i = 0; i < 4; i++) {
        int row = bm + (ty << 2) + i;
        if (row < M) {
            float4 ol, orr;
            ol.x = accl[i][0] + l4[0]; ol.y = accl[i][1] + l4[1];
            ol.z = accl[i][2] + l4[2]; ol.w = accl[i][3] + l4[3];
            orr.x = accr[i][0] + r4[0]; orr.y = accr[i][1] + r4[1];
            orr.z = accr[i][2] + r4[2]; orr.w = accr[i][3] + r4[3];
            *reinterpret_cast<float4*>(Cl + (size_t)row * 128 + col0) = ol;
            *reinterpret_cast<float4*>(Cr + (size_t)row * 128 + col0) = orr;
        }
    }
}

// ---------------- head GEMM fused with output layer ----------------
__global__ void __launch_bounds__(256) gemm_head(const float* __restrict__ A,
                                                 const float* __restrict__ W,
                                                 const float* __restrict__ bias,
                                                 const float* __restrict__ W2,
                                                 const float* __restrict__ b2,
                                                 float* __restrict__ out, int M) {
    __shared__ __align__(16) float As[32][68];
    __shared__ __align__(16) float Ws[32][68];
    const int tid = threadIdx.x;
    const int bm = blockIdx.x * 64;
    const int bp = blockIdx.y * 64;
    const int tx = tid & 15;
    const int ty = tid >> 4;
    float acc[4][4];
#pragma unroll
    for (int i = 0; i < 4; i++)
#pragma unroll
        for (int j = 0; j < 4; j++) acc[i][j] = 0.f;

    const int r = tid >> 3;
    const int kk = (tid & 7) * 4;

    for (int k0 = 0; k0 < 128; k0 += 32) {
#pragma unroll
        for (int rr = 0; rr < 64; rr += 32) {
            int row = bm + r + rr;
            float4 v = (row < M) ? *reinterpret_cast<const float4*>(A + (size_t)row * 128 + k0 + kk)
                                 : make_float4(0.f, 0.f, 0.f, 0.f);
            As[kk + 0][r + rr] = v.x;
            As[kk + 1][r + rr] = v.y;
            As[kk + 2][r + rr] = v.z;
            As[kk + 3][r + rr] = v.w;
            float4 wv = *reinterpret_cast<const float4*>(W + (size_t)(bp + r + rr) * 128 + k0 + kk);
            Ws[kk + 0][r + rr] = wv.x;
            Ws[kk + 1][r + rr] = wv.y;
            Ws[kk + 2][r + rr] = wv.z;
            Ws[kk + 3][r + rr] = wv.w;
        }
        __syncthreads();
#pragma unroll
        for (int k = 0; k < 32; k++) {
            const float4 av = *reinterpret_cast<const float4*>(&As[k][ty << 2]);
            const float4 wv = *reinterpret_cast<const float4*>(&Ws[k][tx << 2]);
            float a4[4] = {av.x, av.y, av.z, av.w};
            float w4[4] = {wv.x, wv.y, wv.z, wv.w};
#pragma unroll
            for (int i = 0; i < 4; i++)
#pragma unroll
                for (int j = 0; j < 4; j++) acc[i][j] += a4[i] * w4[j];
        }
        __syncthreads();
    }

    const int col0 = bp + (tx << 2);
    const float4 bv = *reinterpret_cast<const float4*>(bias + col0);
    const float4 w2 = *reinterpret_cast<const float4*>(W2 + col0);
    float b4[4] = {bv.x, bv.y, bv.z, bv.w};
    float w24[4] = {w2.x, w2.y, w2.z, w2.w};
    const float bout = (bp == 0) ? b2[0] : 0.f;
#pragma unroll
    for (int i = 0; i < 4; i++) {
        int row = bm + (ty << 2) + i;
        float p = fmaxf(acc[i][0] + b4[0], 0.f) * w24[0]
                + fmaxf(acc[i][1] + b4[1], 0.f) * w24[1]
                + fmaxf(acc[i][2] + b4[2], 0.f) * w24[2]
                + fmaxf(acc[i][3] + b4[3], 0.f) * w24[3];
#pragma unroll
        for (int o = 8; o; o >>= 1) p += __shfl_xor_sync(0xffffffffu, p, o);
        if (tx == 0 && row < M) atomicAdd(out + row, p + bout);
    }
}

// ---------------- edge logits: 2 edges per warp (16 lanes each) for 2x MLP ----------
__global__ void __launch_bounds__(256) edge_kernel(const int* __restrict__ ei,
                                                   const float* __restrict__ att) {
    int e = blockIdx.x * 16 + (threadIdx.x >> 4);
    if (e >= E2) return;
    int sub = threadIdx.x & 15;   // 16 lanes per edge, 8 cols each
    int src, dst;
    if (e < EE) {
        src = clampN(ei[e]);
        dst = clampN(ei[EE + e]);
    } else {
        src = e - EE;
        dst = src;
    }
    const float4* xlp = reinterpret_cast<const float4*>(g_xl + (size_t)src * HH + sub * 8);
    const float4* xrp = reinterpret_cast<const float4*>(g_xr + (size_t)dst * HH + sub * 8);
    const float4* atp = reinterpret_cast<const float4*>(att + sub * 8);
    float4 a0 = xlp[0], a1 = xlp[1];
    float4 b0 = xrp[0], b1 = xrp[1];
    float4 t0 = atp[0], t1 = atp[1];
    float s = lrelu(a0.x + b0.x) * t0.x + lrelu(a0.y + b0.y) * t0.y +
              lrelu(a0.z + b0.z) * t0.z + lrelu(a0.w + b0.w) * t0.w +
              lrelu(a1.x + b1.x) * t1.x + lrelu(a1.y + b1.y) * t1.y +
              lrelu(a1.z + b1.z) * t1.z + lrelu(a1.w + b1.w) * t1.w;
#pragma unroll
    for (int o = 8; o; o >>= 1) s += __shfl_xor_sync(0xffffffffu, s, o);
    if (sub == 0) {
        float ez = __expf(s);
        g_ez[e] = ez;
        atomicAdd(&g_denom[dst], ez);
        atomicAdd(&g_count[dst], 1);
    }
}

// ---------------- exclusive scan (1024 threads) ----------------
__global__ void __launch_bounds__(1024) scan_kernel() {
    __shared__ int sh[1024];
    const int t = threadIdx.x;
    const int PER = 10;
    const int base = t * PER;
    int s = 0;
    for (int i = 0; i < PER; i++) {
        int idx = base + i;
        if (idx < NN) s += g_count[idx];
    }
    sh[t] = s;
    __syncthreads();
    for (int o = 1; o < 1024; o <<= 1) {
        int v = (t >= o) ? sh[t - o] : 0;
        __syncthreads();
        sh[t] += v;
        __syncthreads();
    }
    int run = sh[t] - s;
    for (int i = 0; i < PER; i++) {
        int idx = base + i;
        if (idx < NN) {
            g_rowstart[idx] = run;
            run += g_count[idx];
        }
    }
    if (t == 1023) g_rowstart[NN] = sh[1023];
}

// ---------------- fill CSR (rowstart doubles as cursor) ----------------
__global__ void fill_kernel(const int* __restrict__ ei) {
    int e = blockIdx.x * blockDim.x + threadIdx.x;
    if (e >= E2) return;
    int src, dst;
    if (e < EE) {
        src = clampN(ei[e]);
        dst = clampN(ei[EE + e]);
    } else {
        src = e - EE;
        dst = src;
    }
    int idx = atomicAdd(&g_rowstart[dst], 1);
    g_csr_src[idx] = src;
    g_csr_ez[idx] = g_ez[e];
}

// ---------------- aggregate (post-scatter rowstart semantics) ----------------
__global__ void __launch_bounds__(128) agg_kernel(const float* __restrict__ bconv) {
    const int n = blockIdx.x;
    const int t = threadIdx.x;
    __shared__ int   ssrc[128];
    __shared__ float sez[128];
    const int s = (n == 0) ? 0 : g_rowstart[n - 1];
    const int e = g_rowstart[n];
    float acc = 0.f;
    for (int p0 = s; p0 < e; p0 += 128) {
        int m = min(128, e - p0);
        if (t < m) {
            ssrc[t] = g_csr_src[p0 + t];
            sez[t] = g_csr_ez[p0 + t];
        }
        __syncthreads();
#pragma unroll 4
        for (int i = 0; i < m; i++) acc += sez[i] * g_xl[(size_t)ssrc[i] * HH + t];
        __syncthreads();
    }
    float v = acc / g_denom[n] + bconv[t];
    g_hgat[(size_t)n * HH + t] = fmaxf(v, 0.f);
}

// ---------------- sequential GRU: exact R9 (best known) ----------
#define HOFF 68
__global__ void __launch_bounds__(384, 1) gru_kernel(const float* __restrict__ Whh,
                                                     const float* __restrict__ bhh,
                                                     const float* __restrict__ h0) {
    __shared__ __align__(16) float hsh[HOFF + 64];
    __shared__ float2 rz2[128];
    const int t = threadIdx.x;
    const int w = t >> 5;
    const int l = t & 31;
    const int half = l >> 4;
    const int ip = w * 16 + (l & 15);
    const int rowA = 2 * ip;
    const int rho = rowA + half;
    const bool isN = (rho < 128);
    const int e = isN ? rho : ((rho < 256) ? (rho - 128) : (rho - 256));
    const int gate = isN ? 2 : ((rho < 256) ? 0 : 1);

    const int wrowA = (rowA < 128) ? (256 + rowA) : (rowA - 128);
    const int wrowB = wrowA + 1;
    ull wa[32], wb[32];
    {
        const ulonglong2* pa = reinterpret_cast<const ulonglong2*>(Whh + (size_t)wrowA * HH + 64 * half);
        const ulonglong2* pb = reinterpret_cast<const ulonglong2*>(Whh + (size_t)wrowB * HH + 64 * half);
#pragma unroll
        for (int k = 0; k < 16; k++) {
            ulonglong2 va = pa[k];
            ulonglong2 vb = pb[k];
            wa[2 * k] = va.x; wa[2 * k + 1] = va.y;
            wb[2 * k] = vb.x; wb[2 * k + 1] = vb.y;
        }
    }
    const float bh = bhh[(rho < 128) ? (256 + rho) : (rho - 128)];
    const float* giBase = g_gi + (size_t)gate * HH + e;

    float hreg = 0.f;
    if (isN) {
        hreg = h0[e];
        hsh[(e < 64) ? e : (HOFF - 64 + e)] = hreg;
    }
    float gi_cur = giBase[0];
    __syncthreads();

    const ulonglong2* hp = reinterpret_cast<const ulonglong2*>(hsh + HOFF * half);
    const int hpos = (e < 64) ? e : (HOFF - 64 + e);

    for (int s = 0; s < NN; s++) {
        float gi_next = 0.f;
        if (s + 1 < NN) gi_next = giBase[(size_t)(s + 1) * (3 * HH)];

        ull a00 = 0ull, a01 = 0ull, a10 = 0ull, a11 = 0ull;
#pragma unroll
        for (int k = 0; k < 16; k++) {
            ulonglong2 c = hp[k];
            a00 = ffma2(wa[2 * k], c.x, a00);
            a01 = ffma2(wa[2 * k + 1], c.y, a01);
            a10 = ffma2(wb[2 * k], c.x, a10);
            a11 = ffma2(wb[2 * k + 1], c.y, a11);
        }
        float d0 = unpack_sum(fadd2(a00, a01));
        float d1 = unpack_sum(fadd2(a10, a11));
        d0 += __shfl_xor_sync(0xffffffffu, d0, 16);
        d1 += __shfl_xor_sync(0xffffffffu, d1, 16);
        float res = (half ? d1 : d0) + bh;

        if (!isN) {
            reinterpret_cast<float*>(rz2)[2 * e + gate] = sigf(gi_cur + res);
        }
        __syncthreads();
        if (isN) {
            float2 v = rz2[e];
            float nc = tanhfast(gi_cur + v.x * res);
            float hnew = nc + v.y * (hreg - nc);
            hreg = hnew;
            hsh[hpos] = hnew;
            g_hseq[(size_t)s * HH + e] = hnew;
        }
        __syncthreads();
        gi_cur = gi_next;
    }
}

// ---------------- launch ----------------
extern "C" void kernel_launch(void* const* d_in, const int* in_sizes, int n_in,
                              void* d_out, int out_size) {
    const float* x      = (const float*)d_in[0];
    const int*   ei     = (const int*)d_in[1];
    const float* Wl     = (const float*)d_in[2];
    const float* bl     = (const float*)d_in[3];
    const float* Wr     = (const float*)d_in[4];
    const float* br     = (const float*)d_in[5];
    const float* att    = (const float*)d_in[6];
    const float* bconv  = (const float*)d_in[7];
    const float* Wih    = (const float*)d_in[8];
    const float* Whh    = (const float*)d_in[9];
    const float* bih    = (const float*)d_in[10];
    const float* bhh    = (const float*)d_in[11];
    const float* h0     = (const float*)d_in[12];
    const float* Wlin   = (const float*)d_in[13];
    const float* blin   = (const float*)d_in[14];
    const float* Wlin2  = (const float*)d_in[15];
    const float* blin2  = (const float*)d_in[16];
    float* out = (float*)d_out;

    float *xl_p, *xr_p, *hgat_p, *gi_p, *hseq_p;
    cudaGetSymbolAddress((void**)&xl_p,   g_xl);
    cudaGetSymbolAddress((void**)&xr_p,   g_xr);
    cudaGetSymbolAddress((void**)&hgat_p, g_hgat);
    cudaGetSymbolAddress((void**)&gi_p,   g_gi);
    cudaGetSymbolAddress((void**)&hseq_p, g_hseq);

    const int MB = (NN + 63) / 64;

    zero_kernel<<<(NN + 255) / 256, 256>>>(out);

    gemm_dual<<<dim3(MB, 2), 256>>>(x, Wl, bl, Wr, br, xl_p, xr_p, NN);

    edge_kernel<<<(E2 + 15) / 16, 256>>>(ei, att);
    scan_kernel<<<1, 1024>>>();
    fill_kernel<<<(E2 + 255) / 256, 256>>>(ei);
    agg_kernel<<<NN, 128>>>(bconv);

    gemm_tn<384, false><<<dim3(MB, 6), 256>>>(hgat_p, Wih, bih, gi_p, NN);

    gru_kernel<<<1, 384>>>(Whh, bhh, h0);

    gemm_head<<<dim3(MB, 2), 256>>>(hseq_p, Wlin, blin, Wlin2, blin2, out, NN);
}

// round 17
// speedup vs baseline: 1.0012x; 1.0012x over previous
#include <cuda_runtime.h>
#include <cstdint>

#define NN 10000
#define HH 128
#define EE 640000
#define E2 (EE + NN)
#define GI_CHUNK 2048   // rows of gi computed before the GRU starts (32 blocks)

typedef unsigned long long ull;

// ---------------- device scratch ----------------
__device__ float g_xl[NN * HH];
__device__ float g_xr[NN * HH];
__device__ float g_ez[E2];
__device__ float g_denom[NN];
__device__ int   g_count[NN];
__device__ int   g_rowstart[NN + 1];
__device__ int   g_csr_src[E2];
__device__ float g_csr_ez[E2];
__device__ float g_hgat[NN * HH];
__device__ float g_gi[NN * 3 * HH];
__device__ float g_hseq[NN * HH];

// ---------------- helpers ----------------
__device__ __forceinline__ ull ffma2(ull a, ull b, ull c) {
    ull d;
    asm("fma.rn.f32x2 %0, %1, %2, %3;" : "=l"(d) : "l"(a), "l"(b), "l"(c));
    return d;
}
__device__ __forceinline__ ull fadd2(ull a, ull b) {
    ull d;
    asm("add.rn.f32x2 %0, %1, %2;" : "=l"(d) : "l"(a), "l"(b));
    return d;
}
__device__ __forceinline__ float unpack_sum(ull a) {
    unsigned lo, hi;
    asm("mov.b64 {%0,%1}, %2;" : "=r"(lo), "=r"(hi) : "l"(a));
    return __uint_as_float(lo) + __uint_as_float(hi);
}
__device__ __forceinline__ float sigf(float x) {
    return __fdividef(1.f, 1.f + __expf(-x));
}
__device__ __forceinline__ float tanhfast(float x) {
    return 2.f * __fdividef(1.f, 1.f + __expf(-2.f * x)) - 1.f;
}
__device__ __forceinline__ float lrelu(float v) {
    return v > 0.f ? v : 0.2f * v;
}
__device__ __forceinline__ int clampN(int v) {
    return v < 0 ? 0 : (v >= NN ? NN - 1 : v);
}

// ---------------- zero init (+ out, for atomic head) ----------------
__global__ void zero_kernel(float* __restrict__ out) {
    int i = blockIdx.x * blockDim.x + threadIdx.x;
    if (i < NN) {
        g_denom[i] = 0.f;
        g_count[i] = 0;
        out[i] = 0.f;
    }
}

// ---------------- GEMM: C[M x P] = A[M x 128] @ W[P x 128]^T + bias ----------------
template <int P, bool RELU>
__global__ void __launch_bounds__(256) gemm_tn(const float* __restrict__ A,
                                               const float* __restrict__ W,
                                               const float* __restrict__ bias,
                                               float* __restrict__ C, int M) {
    __shared__ __align__(16) float As[32][68];
    __shared__ __align__(16) float Ws[32][68];
    const int tid = threadIdx.x;
    const int bm = blockIdx.x * 64;
    const int bp = blockIdx.y * 64;
    const int tx = tid & 15;
    const int ty = tid >> 4;
    float acc[4][4];
#pragma unroll
    for (int i = 0; i < 4; i++)
#pragma unroll
        for (int j = 0; j < 4; j++) acc[i][j] = 0.f;

    const int r = tid >> 3;
    const int kk = (tid & 7) * 4;

    for (int k0 = 0; k0 < 128; k0 += 32) {
#pragma unroll
        for (int rr = 0; rr < 64; rr += 32) {
            int row = bm + r + rr;
            float4 v = (row < M) ? *reinterpret_cast<const float4*>(A + (size_t)row * 128 + k0 + kk)
                                 : make_float4(0.f, 0.f, 0.f, 0.f);
            As[kk + 0][r + rr] = v.x;
            As[kk + 1][r + rr] = v.y;
            As[kk + 2][r + rr] = v.z;
            As[kk + 3][r + rr] = v.w;
            float4 wv = *reinterpret_cast<const float4*>(W + (size_t)(bp + r + rr) * 128 + k0 + kk);
            Ws[kk + 0][r + rr] = wv.x;
            Ws[kk + 1][r + rr] = wv.y;
            Ws[kk + 2][r + rr] = wv.z;
            Ws[kk + 3][r + rr] = wv.w;
        }
        __syncthreads();
#pragma unroll
        for (int k = 0; k < 32; k++) {
            const float4 av = *reinterpret_cast<const float4*>(&As[k][ty << 2]);
            const float4 wv = *reinterpret_cast<const float4*>(&Ws[k][tx << 2]);
            float a4[4] = {av.x, av.y, av.z, av.w};
            float w4[4] = {wv.x, wv.y, wv.z, wv.w};
#pragma unroll
            for (int i = 0; i < 4; i++)
#pragma unroll
                for (int j = 0; j < 4; j++) acc[i][j] += a4[i] * w4[j];
        }
        __syncthreads();
    }

    const int col0 = bp + (tx << 2);
    const float4 bv = *reinterpret_cast<const float4*>(bias + col0);
    float b4[4] = {bv.x, bv.y, bv.z, bv.w};
#pragma unroll
    for (int i = 0; i < 4; i++) {
        int row = bm + (ty << 2) + i;
        if (row < M) {
            float4 o;
            float v0 = acc[i][0] + b4[0];
            float v1 = acc[i][1] + b4[1];
            float v2 = acc[i][2] + b4[2];
            float v3 = acc[i][3] + b4[3];
            if (RELU) {
                v0 = fmaxf(v0, 0.f); v1 = fmaxf(v1, 0.f);
                v2 = fmaxf(v2, 0.f); v3 = fmaxf(v3, 0.f);
            }
            o.x = v0; o.y = v1; o.z = v2; o.w = v3;
            *reinterpret_cast<float4*>(C + (size_t)row * P + col0) = o;
        }
    }
}

// ---------------- dual GEMM: xl = A@Wl^T+bl, xr = A@Wr^T+br (A tile loaded once) ----
__global__ void __launch_bounds__(256) gemm_dual(const float* __restrict__ A,
                                                 const float* __restrict__ Wl,
                                                 const float* __restrict__ bl,
                                                 const float* __restrict__ Wr,
                                                 const float* __restrict__ br,
                                                 float* __restrict__ Cl,
                                                 float* __restrict__ Cr, int M) {
    __shared__ __align__(16) float As[32][68];
    __shared__ __align__(16) float Wsl[32][68];
    __shared__ __align__(16) float Wsr[32][68];
    const int tid = threadIdx.x;
    const int bm = blockIdx.x * 64;
    const int bp = blockIdx.y * 64;
    const int tx = tid & 15;
    const int ty = tid >> 4;
    float accl[4][4], accr[4][4];
#pragma unroll
    for (int i = 0; i < 4; i++)
#pragma unroll
        for (int j = 0; j < 4; j++) { accl[i][j] = 0.f; accr[i][j] = 0.f; }

    const int r = tid >> 3;
    const int kk = (tid & 7) * 4;

    for (int k0 = 0; k0 < 128; k0 += 32) {
#pragma unroll
        for (int rr = 0; rr < 64; rr += 32) {
            int row = bm + r + rr;
            float4 v = (row < M) ? *reinterpret_cast<const float4*>(A + (size_t)row * 128 + k0 + kk)
                                 : make_float4(0.f, 0.f, 0.f, 0.f);
            As[kk + 0][r + rr] = v.x;
            As[kk + 1][r + rr] = v.y;
            As[kk + 2][r + rr] = v.z;
            As[kk + 3][r + rr] = v.w;
            float4 wl = *reinterpret_cast<const float4*>(Wl + (size_t)(bp + r + rr) * 128 + k0 + kk);
            Wsl[kk + 0][r + rr] = wl.x;
            Wsl[kk + 1][r + rr] = wl.y;
            Wsl[kk + 2][r + rr] = wl.z;
            Wsl[kk + 3][r + rr] = wl.w;
            float4 wr = *reinterpret_cast<const float4*>(Wr + (size_t)(bp + r + rr) * 128 + k0 + kk);
            Wsr[kk + 0][r + rr] = wr.x;
            Wsr[kk + 1][r + rr] = wr.y;
            Wsr[kk + 2][r + rr] = wr.z;
            Wsr[kk + 3][r + rr] = wr.w;
        }
        __syncthreads();
#pragma unroll
        for (int k = 0; k < 32; k++) {
            const float4 av = *reinterpret_cast<const float4*>(&As[k][ty << 2]);
            const float4 wl = *reinterpret_cast<const float4*>(&Wsl[k][tx << 2]);
            const float4 wr = *reinterpret_cast<const float4*>(&Wsr[k][tx << 2]);
            float a4[4] = {av.x, av.y, av.z, av.w};
            float l4[4] = {wl.x, wl.y, wl.z, wl.w};
            float r4[4] = {wr.x, wr.y, wr.z, wr.w};
#pragma unroll
            for (int i = 0; i < 4; i++)
#pragma unroll
                for (int j = 0; j < 4; j++) {
                    accl[i][j] += a4[i] * l4[j];
                    accr[i][j] += a4[i] * r4[j];
                }
        }
        __syncthreads();
    }

    const int col0 = bp + (tx << 2);
    const float4 bvl = *reinterpret_cast<const float4*>(bl + col0);
    const float4 bvr = *reinterpret_cast<const float4*>(br + col0);
    float l4[4] = {bvl.x, bvl.y, bvl.z, bvl.w};
    float r4[4] = {bvr.x, bvr.y, bvr.z, bvr.w};
#pragma unroll
    for (int i = 0; i < 4; i++) {
        int row = bm + (ty << 2) + i;
        if (row < M) {
            float4 ol, orr;
            ol.x = accl[i][0] + l4[0]; ol.y = accl[i][1] + l4[1];
            ol.z = accl[i][2] + l4[2]; ol.w = accl[i][3] + l4[3];
            orr.x = accr[i][0] + r4[0]; orr.y = accr[i][1] + r4[1];
            orr.z = accr[i][2] + r4[2]; orr.w = accr[i][3] + r4[3];
            *reinterpret_cast<float4*>(Cl + (size_t)row * 128 + col0) = ol;
            *reinterpret_cast<float4*>(Cr + (size_t)row * 128 + col0) = orr;
        }
    }
}

// ---------------- head GEMM fused with output layer ----------------
__global__ void __launch_bounds__(256) gemm_head(const float* __restrict__ A,
                                                 const float* __restrict__ W,
                                                 const float* __restrict__ bias,
                                                 const float* __restrict__ W2,
                                                 const float* __restrict__ b2,
                                                 float* __restrict__ out, int M) {
    __shared__ __align__(16) float As[32][68];
    __shared__ __align__(16) float Ws[32][68];
    const int tid = threadIdx.x;
    const int bm = blockIdx.x * 64;
    const int bp = blockIdx.y * 64;
    const int tx = tid & 15;
    const int ty = tid >> 4;
    float acc[4][4];
#pragma unroll
    for (int i = 0; i < 4; i++)
#pragma unroll
        for (int j = 0; j < 4; j++) acc[i][j] = 0.f;

    const int r = tid >> 3;
    const int kk = (tid & 7) * 4;

    for (int k0 = 0; k0 < 128; k0 += 32) {
#pragma unroll
        for (int rr = 0; rr < 64; rr += 32) {
            int row = bm + r + rr;
            float4 v = (row < M) ? *reinterpret_cast<const float4*>(A + (size_t)row * 128 + k0 + kk)
                                 : make_float4(0.f, 0.f, 0.f, 0.f);
            As[kk + 0][r + rr] = v.x;
            As[kk + 1][r + rr] = v.y;
            As[kk + 2][r + rr] = v.z;
            As[kk + 3][r + rr] = v.w;
            float4 wv = *reinterpret_cast<const float4*>(W + (size_t)(bp + r + rr) * 128 + k0 + kk);
            Ws[kk + 0][r + rr] = wv.x;
            Ws[kk + 1][r + rr] = wv.y;
            Ws[kk + 2][r + rr] = wv.z;
            Ws[kk + 3][r + rr] = wv.w;
        }
        __syncthreads();
#pragma unroll
        for (int k = 0; k < 32; k++) {
            const float4 av = *reinterpret_cast<const float4*>(&As[k][ty << 2]);
            const float4 wv = *reinterpret_cast<const float4*>(&Ws[k][tx << 2]);
            float a4[4] = {av.x, av.y, av.z, av.w};
            float w4[4] = {wv.x, wv.y, wv.z, wv.w};
#pragma unroll
            for (int i = 0; i < 4; i++)
#pragma unroll
                for (int j = 0; j < 4; j++) acc[i][j] += a4[i] * w4[j];
        }
        __syncthreads();
    }

    const int col0 = bp + (tx << 2);
    const float4 bv = *reinterpret_cast<const float4*>(bias + col0);
    const float4 w2 = *reinterpret_cast<const float4*>(W2 + col0);
    float b4[4] = {bv.x, bv.y, bv.z, bv.w};
    float w24[4] = {w2.x, w2.y, w2.z, w2.w};
    const float bout = (bp == 0) ? b2[0] : 0.f;
#pragma unroll
    for (int i = 0; i < 4; i++) {
        int row = bm + (ty << 2) + i;
        float p = fmaxf(acc[i][0] + b4[0], 0.f) * w24[0]
                + fmaxf(acc[i][1] + b4[1], 0.f) * w24[1]
                + fmaxf(acc[i][2] + b4[2], 0.f) * w24[2]
                + fmaxf(acc[i][3] + b4[3], 0.f) * w24[3];
#pragma unroll
        for (int o = 8; o; o >>= 1) p += __shfl_xor_sync(0xffffffffu, p, o);
        if (tx == 0 && row < M) atomicAdd(out + row, p + bout);
    }
}

// ---------------- edge logits (R15 proven path: 1 edge per warp) ----------------
__global__ void __launch_bounds__(256) edge_kernel(const int* __restrict__ ei,
                                                   const float* __restrict__ att) {
    int e = blockIdx.x * 8 + (threadIdx.x >> 5);
    if (e >= E2) return;
    int lane = threadIdx.x & 31;
    int src, dst;
    if (e < EE) {
        src = clampN(ei[e]);
        dst = clampN(ei[EE + e]);
    } else {
        src = e - EE;
        dst = src;
    }
    const float4 a = *reinterpret_cast<const float4*>(g_xl + (size_t)src * HH + lane * 4);
    const float4 b = *reinterpret_cast<const float4*>(g_xr + (size_t)dst * HH + lane * 4);
    const float4 at = *reinterpret_cast<const float4*>(att + lane * 4);
    float s = lrelu(a.x + b.x) * at.x + lrelu(a.y + b.y) * at.y +
              lrelu(a.z + b.z) * at.z + lrelu(a.w + b.w) * at.w;
#pragma unroll
    for (int o = 16; o; o >>= 1) s += __shfl_xor_sync(0xffffffffu, s, o);
    if (lane == 0) {
        float ez = __expf(s);
        g_ez[e] = ez;
        atomicAdd(&g_denom[dst], ez);
        atomicAdd(&g_count[dst], 1);
    }
}

// ---------------- exclusive scan (1024 threads) ----------------
__global__ void __launch_bounds__(1024) scan_kernel() {
    __shared__ int sh[1024];
    const int t = threadIdx.x;
    const int PER = 10;
    const int base = t * PER;
    int s = 0;
    for (int i = 0; i < PER; i++) {
        int idx = base + i;
        if (idx < NN) s += g_count[idx];
    }
    sh[t] = s;
    __syncthreads();
    for (int o = 1; o < 1024; o <<= 1) {
        int v = (t >= o) ? sh[t - o] : 0;
        __syncthreads();
        sh[t] += v;
        __syncthreads();
    }
    int run = sh[t] - s;
    for (int i = 0; i < PER; i++) {
        int idx = base + i;
        if (idx < NN) {
            g_rowstart[idx] = run;
            run += g_count[idx];
        }
    }
    if (t == 1023) g_rowstart[NN] = sh[1023];
}

// ---------------- fill CSR (rowstart doubles as cursor) ----------------
__global__ void fill_kernel(const int* __restrict__ ei) {
    int e = blockIdx.x * blockDim.x + threadIdx.x;
    if (e >= E2) return;
    int src, dst;
    if (e < EE) {
        src = clampN(ei[e]);
        dst = clampN(ei[EE + e]);
    } else {
        src = e - EE;
        dst = src;
    }
    int idx = atomicAdd(&g_rowstart[dst], 1);
    g_csr_src[idx] = src;
    g_csr_ez[idx] = g_ez[e];
}

// ---------------- aggregate (post-scatter rowstart semantics) ----------------
__global__ void __launch_bounds__(128) agg_kernel(const float* __restrict__ bconv) {
    const int n = blockIdx.x;
    const int t = threadIdx.x;
    __shared__ int   ssrc[128];
    __shared__ float sez[128];
    const int s = (n == 0) ? 0 : g_rowstart[n - 1];
    const int e = g_rowstart[n];
    float acc = 0.f;
    for (int p0 = s; p0 < e; p0 += 128) {
        int m = min(128, e - p0);
        if (t < m) {
            ssrc[t] = g_csr_src[p0 + t];
            sez[t] = g_csr_ez[p0 + t];
        }
        __syncthreads();
#pragma unroll 4
        for (int i = 0; i < m; i++) acc += sez[i] * g_xl[(size_t)ssrc[i] * HH + t];
        __syncthreads();
    }
    float v = acc / g_denom[n] + bconv[t];
    g_hgat[(size_t)n * HH + t] = fmaxf(v, 0.f);
}

// ---------------- sequential GRU: exact R9 (best known) ----------
#define HOFF 68
__global__ void __launch_bounds__(384, 1) gru_kernel(const float* __restrict__ Whh,
                                                     const float* __restrict__ bhh,
                                                     const float* __restrict__ h0) {
    __shared__ __align__(16) float hsh[HOFF + 64];
    __shared__ float2 rz2[128];
    const int t = threadIdx.x;
    const int w = t >> 5;
    const int l = t & 31;
    const int half = l >> 4;
    const int ip = w * 16 + (l & 15);
    const int rowA = 2 * ip;
    const int rho = rowA + half;
    const bool isN = (rho < 128);
    const int e = isN ? rho : ((rho < 256) ? (rho - 128) : (rho - 256));
    const int gate = isN ? 2 : ((rho < 256) ? 0 : 1);

    const int wrowA = (rowA < 128) ? (256 + rowA) : (rowA - 128);
    const int wrowB = wrowA + 1;
    ull wa[32], wb[32];
    {
        const ulonglong2* pa = reinterpret_cast<const ulonglong2*>(Whh + (size_t)wrowA * HH + 64 * half);
        const ulonglong2* pb = reinterpret_cast<const ulonglong2*>(Whh + (size_t)wrowB * HH + 64 * half);
#pragma unroll
        for (int k = 0; k < 16; k++) {
            ulonglong2 va = pa[k];
            ulonglong2 vb = pb[k];
            wa[2 * k] = va.x; wa[2 * k + 1] = va.y;
            wb[2 * k] = vb.x; wb[2 * k + 1] = vb.y;
        }
    }
    const float bh = bhh[(rho < 128) ? (256 + rho) : (rho - 128)];
    const float* giBase = g_gi + (size_t)gate * HH + e;

    float hreg = 0.f;
    if (isN) {
        hreg = h0[e];
        hsh[(e < 64) ? e : (HOFF - 64 + e)] = hreg;
    }
    float gi_cur = giBase[0];
    __syncthreads();

    const ulonglong2* hp = reinterpret_cast<const ulonglong2*>(hsh + HOFF * half);
    const int hpos = (e < 64) ? e : (HOFF - 64 + e);

    for (int s = 0; s < NN; s++) {
        float gi_next = 0.f;
        if (s + 1 < NN) gi_next = giBase[(size_t)(s + 1) * (3 * HH)];

        ull a00 = 0ull, a01 = 0ull, a10 = 0ull, a11 = 0ull;
#pragma unroll
        for (int k = 0; k < 16; k++) {
            ulonglong2 c = hp[k];
            a00 = ffma2(wa[2 * k], c.x, a00);
            a01 = ffma2(wa[2 * k + 1], c.y, a01);
            a10 = ffma2(wb[2 * k], c.x, a10);
            a11 = ffma2(wb[2 * k + 1], c.y, a11);
        }
        float d0 = unpack_sum(fadd2(a00, a01));
        float d1 = unpack_sum(fadd2(a10, a11));
        d0 += __shfl_xor_sync(0xffffffffu, d0, 16);
        d1 += __shfl_xor_sync(0xffffffffu, d1, 16);
        float res = (half ? d1 : d0) + bh;

        if (!isN) {
            reinterpret_cast<float*>(rz2)[2 * e + gate] = sigf(gi_cur + res);
        }
        __syncthreads();
        if (isN) {
            float2 v = rz2[e];
            float nc = tanhfast(gi_cur + v.x * res);
            float hnew = nc + v.y * (hreg - nc);
            hreg = hnew;
            hsh[hpos] = hnew;
            g_hseq[(size_t)s * HH + e] = hnew;
        }
        __syncthreads();
        gi_cur = gi_next;
    }
}

// ---------------- launch ----------------
extern "C" void kernel_launch(void* const* d_in, const int* in_sizes, int n_in,
                              void* d_out, int out_size) {
    const float* x      = (const float*)d_in[0];
    const int*   ei     = (const int*)d_in[1];
    const float* Wl     = (const float*)d_in[2];
    const float* bl     = (const float*)d_in[3];
    const float* Wr     = (const float*)d_in[4];
    const float* br     = (const float*)d_in[5];
    const float* att    = (const float*)d_in[6];
    const float* bconv  = (const float*)d_in[7];
    const float* Wih    = (const float*)d_in[8];
    const float* Whh    = (const float*)d_in[9];
    const float* bih    = (const float*)d_in[10];
    const float* bhh    = (const float*)d_in[11];
    const float* h0     = (const float*)d_in[12];
    const float* Wlin   = (const float*)d_in[13];
    const float* blin   = (const float*)d_in[14];
    const float* Wlin2  = (const float*)d_in[15];
    const float* blin2  = (const float*)d_in[16];
    float* out = (float*)d_out;

    float *xl_p, *xr_p, *hgat_p, *gi_p, *hseq_p;
    cudaGetSymbolAddress((void**)&xl_p,   g_xl);
    cudaGetSymbolAddress((void**)&xr_p,   g_xr);
    cudaGetSymbolAddress((void**)&hgat_p, g_hgat);
    cudaGetSymbolAddress((void**)&gi_p,   g_gi);
    cudaGetSymbolAddress((void**)&hseq_p, g_hseq);

    // side stream + fork/join events, created once on the first (uncaptured)
    // correctness call; reused inside graph capture (standard capture-fork).
    static cudaStream_t s2 = nullptr;
    static cudaEvent_t ev_fork = nullptr, ev_join = nullptr;
    if (!s2) {
        cudaStreamCreateWithFlags(&s2, cudaStreamNonBlocking);
        cudaEventCreateWithFlags(&ev_fork, cudaEventDisableTiming);
        cudaEventCreateWithFlags(&ev_join, cudaEventDisableTiming);
    }

    const int MB = (NN + 63) / 64;          // 157
    const int MB1 = GI_CHUNK / 64;          // 32 blocks -> rows [0, 2048)
    const int MB2 = MB - MB1;               // 125 blocks -> rows [2048, 10000)

    zero_kernel<<<(NN + 255) / 256, 256>>>(out);

    gemm_dual<<<dim3(MB, 2), 256>>>(x, Wl, bl, Wr, br, xl_p, xr_p, NN);

    edge_kernel<<<(E2 + 7) / 8, 256>>>(ei, att);
    scan_kernel<<<1, 1024>>>();
    fill_kernel<<<(E2 + 255) / 256, 256>>>(ei);
    agg_kernel<<<NN, 128>>>(bconv);

    // gi chunk 1 (rows [0, GI_CHUNK)) on the main stream -- ready before GRU starts
    gemm_tn<384, false><<<dim3(MB1, 6), 256>>>(hgat_p, Wih, bih, gi_p, GI_CHUNK);

    // fork: gi chunk 2 (rows [GI_CHUNK, NN)) on side stream, concurrent with GRU.
    // GRU consumes ~1 row / 460ns -> reaches row GI_CHUNK at ~0.94ms; chunk 2
    // finishes in ~120us on the 147 free SMs (7x margin).
    cudaEventRecord(ev_fork, 0);
    cudaStreamWaitEvent(s2, ev_fork, 0);
    gemm_tn<384, false><<<dim3(MB2, 6), 256, 0, s2>>>(
        hgat_p + (size_t)GI_CHUNK * HH, Wih, bih,
        gi_p + (size_t)GI_CHUNK * 3 * HH, NN - GI_CHUNK);
    cudaEventRecord(ev_join, s2);

    gru_kernel<<<1, 384>>>(Whh, bhh, h0);

    // join side stream before the head (graph well-formedness)
    cudaStreamWaitEvent(0, ev_join, 0);
    gemm_head<<<dim3(MB, 2), 256>>>(hseq_p, Wlin, blin, Wlin2, blin2, out, NN);
}